// round 8
// baseline (speedup 1.0000x reference)
#include <cuda_runtime.h>
#include <cuda_bf16.h>

#define C_DIM   10000
#define B_DIM   8192
#define M_SCALE 4.0f
#define THREADS 256
#define N4      (C_DIM / 4)               // 2500 float4 per row
#define FULL_IT (N4 / THREADS)            // 9
#define TAIL_N  (N4 - FULL_IT * THREADS)  // 196
#define NBLK    (B_DIM / 2)               // 4096 blocks, 2 rows each

// Fixed-point (Q32) deterministic accumulator + completion counter.
__device__ unsigned long long g_acc  = 0ULL;
__device__ unsigned int       g_done = 0u;

__device__ __forceinline__ float block_reduce(float s, float* warp_sums,
                                              int lane, int wid)
{
    #pragma unroll
    for (int off = 16; off > 0; off >>= 1)
        s += __shfl_xor_sync(0xFFFFFFFFu, s, off);
    if (lane == 0) warp_sums[wid] = s;
    __syncthreads();
    float t = 0.0f;
    if (wid == 0) {
        t = (lane < THREADS / 32) ? warp_sums[lane] : 0.0f;
        #pragma unroll
        for (int off = 4; off > 0; off >>= 1)
            t += __shfl_xor_sync(0xFFFFFFFFu, t, off);
    }
    return t;
}

__global__ __launch_bounds__(THREADS, 5) void ems_fused_kernel(
    const float* __restrict__ inputs,
    const int* __restrict__ targets,   // int32 (JAX default int width)
    float* __restrict__ out)
{
    const int row0 = blockIdx.x * 2;
    const int row1 = row0 + 1;
    const int tid  = threadIdx.x;
    const int lane = tid & 31, wid = tid >> 5;

    const float4* __restrict__ p0 =
        reinterpret_cast<const float4*>(inputs + (size_t)row0 * C_DIM);
    const float4* __restrict__ p1 =
        reinterpret_cast<const float4*>(inputs + (size_t)row1 * C_DIM);
    const bool has_tail = (tid < TAIL_N);

    __shared__ float warp_sums[THREADS / 32];

    // ---- row0: front-batched loads (MLP ~10, the proven R6 form) ----
    float4 v[FULL_IT];
    #pragma unroll
    for (int k = 0; k < FULL_IT; k++)
        v[k] = __ldg(&p0[tid + k * THREADS]);
    float4 vt = has_tail ? __ldg(&p0[FULL_IT * THREADS + tid])
                         : make_float4(0.f, 0.f, 0.f, 0.f);

    // ---- hoisted target gathers for both rows (lane0/warp0 only);
    //      dependent-load chain overlaps the entire mainloop ----
    float xt0 = 0.0f, xt1 = 0.0f;
    if (tid == 0) {
        const int t0 = __ldg(&targets[row0]);
        const int t1 = __ldg(&targets[row1]);
        xt0 = __ldg(inputs + (size_t)row0 * C_DIM + t0);
        xt1 = __ldg(inputs + (size_t)row1 * C_DIM + t1);
    }

    // ---- exp-sum row0 ----
    float sA = 0.0f;
    #pragma unroll
    for (int k = 0; k < FULL_IT; k++) {
        sA += __expf(v[k].x);
        sA += __expf(v[k].y);
        sA += __expf(v[k].z);
        sA += __expf(v[k].w);
    }
    if (has_tail) {
        sA += __expf(vt.x); sA += __expf(vt.y);
        sA += __expf(vt.z); sA += __expf(vt.w);
    }

    // ---- issue row1 loads BEFORE row0's reduction: their DRAM latency
    //      overlaps the reduction + epilogue tail ----
    float4 w[FULL_IT];
    #pragma unroll
    for (int k = 0; k < FULL_IT; k++)
        w[k] = __ldg(&p1[tid + k * THREADS]);
    float4 wt = has_tail ? __ldg(&p1[FULL_IT * THREADS + tid])
                         : make_float4(0.f, 0.f, 0.f, 0.f);

    // ---- reduce + epilogue row0 ----
    float tA = block_reduce(sA, warp_sums, lane, wid);
    if (tid == 0) {
        const float xtm = M_SCALE * xt0;
        const float sp  = tA - __expf(xt0) + __expf(xtm);
        const float loss = __logf(sp) - xtm;
        const long long q = __double2ll_rn((double)loss * 4294967296.0);
        atomicAdd(&g_acc, (unsigned long long)q);
    }
    __syncthreads();   // protect warp_sums reuse

    // ---- exp-sum row1 ----
    float sB = 0.0f;
    #pragma unroll
    for (int k = 0; k < FULL_IT; k++) {
        sB += __expf(w[k].x);
        sB += __expf(w[k].y);
        sB += __expf(w[k].z);
        sB += __expf(w[k].w);
    }
    if (has_tail) {
        sB += __expf(wt.x); sB += __expf(wt.y);
        sB += __expf(wt.z); sB += __expf(wt.w);
    }

    // ---- reduce + epilogue row1 + completion ----
    float tB = block_reduce(sB, warp_sums, lane, wid);
    if (tid == 0) {
        const float xtm = M_SCALE * xt1;
        const float sp  = tB - __expf(xt1) + __expf(xtm);
        const float loss = __logf(sp) - xtm;
        const long long q = __double2ll_rn((double)loss * 4294967296.0);
        atomicAdd(&g_acc, (unsigned long long)q);
        __threadfence();

        const unsigned int prev = atomicAdd(&g_done, 1u);
        if (prev == NBLK - 1) {
            const long long total = (long long)atomicAdd(&g_acc, 0ULL);
            out[0] = (float)((double)total * (1.0 / 4294967296.0) / (double)B_DIM);
            // Reset for the next graph replay (stream-ordered before it).
            atomicExch(&g_acc, 0ULL);
            atomicExch(&g_done, 0u);
        }
    }
}

extern "C" void kernel_launch(void* const* d_in, const int* in_sizes, int n_in,
                              void* d_out, int out_size)
{
    const float* inputs = (const float*)d_in[0];
    const int* targets = (const int*)d_in[1];
    float* out = (float*)d_out;

    ems_fused_kernel<<<NBLK, THREADS>>>(inputs, targets, out);
}

// round 9
// speedup vs baseline: 1.0604x; 1.0604x over previous
#include <cuda_runtime.h>
#include <cuda_bf16.h>

#define C_DIM   10000
#define B_DIM   8192
#define M_SCALE 4.0f
#define THREADS 256
#define N4      (C_DIM / 4)               // 2500 float4 per row
#define FULL_IT (N4 / THREADS)            // 9
#define TAIL_N  (N4 - FULL_IT * THREADS)  // 196

// Per-row loss scratch; overwritten every replay, no reset needed.
__device__ float g_row_loss[B_DIM];

// ---------------- Kernel 1: per-row loss (exact R6 mainloop, STG finish) ----
__global__ __launch_bounds__(THREADS) void ems_row_kernel(
    const float* __restrict__ inputs,
    const int* __restrict__ targets)   // int32 (JAX default int width)
{
    const int row = blockIdx.x;
    const int tid = threadIdx.x;
    const float4* __restrict__ rowp =
        reinterpret_cast<const float4*>(inputs + (size_t)row * C_DIM);

    // Front-batched loads: 9 full + predicated tail (MLP ~10) — proven fastest loop.
    float4 v[FULL_IT];
    #pragma unroll
    for (int k = 0; k < FULL_IT; k++)
        v[k] = __ldg(&rowp[tid + k * THREADS]);

    const bool has_tail = (tid < TAIL_N);
    float4 vt = has_tail ? __ldg(&rowp[FULL_IT * THREADS + tid])
                         : make_float4(0.f, 0.f, 0.f, 0.f);

    float s = 0.0f;
    #pragma unroll
    for (int k = 0; k < FULL_IT; k++) {
        s += __expf(v[k].x);
        s += __expf(v[k].y);
        s += __expf(v[k].z);
        s += __expf(v[k].w);
    }
    if (has_tail) {
        s += __expf(vt.x);
        s += __expf(vt.y);
        s += __expf(vt.z);
        s += __expf(vt.w);
    }

    // ---- block reduction ----
    #pragma unroll
    for (int off = 16; off > 0; off >>= 1)
        s += __shfl_xor_sync(0xFFFFFFFFu, s, off);

    __shared__ float warp_sums[THREADS / 32];
    const int lane = tid & 31, wid = tid >> 5;
    if (lane == 0) warp_sums[wid] = s;
    __syncthreads();

    if (wid == 0) {
        float t = (lane < THREADS / 32) ? warp_sums[lane] : 0.0f;
        #pragma unroll
        for (int off = 4; off > 0; off >>= 1)
            t += __shfl_xor_sync(0xFFFFFFFFu, t, off);
        if (lane == 0) {
            const int tgt = targets[row];
            const float xt  = __ldg(inputs + (size_t)row * C_DIM + tgt);
            const float xtm = M_SCALE * xt;
            // replace exp(x_t) by exp(4*x_t) in the row sum
            const float sp = t - __expf(xt) + __expf(xtm);
            g_row_loss[row] = __logf(sp) - xtm;   // plain STG: no fence, no atomics
        }
    }
}

// ---------------- Kernel 2: mean of 8192 floats (single block, MLP=8) -------
__global__ __launch_bounds__(THREADS) void ems_reduce_kernel(float* __restrict__ out)
{
    const int tid = threadIdx.x;
    const float4* __restrict__ p = reinterpret_cast<const float4*>(g_row_loss);
    // 8192 floats = 2048 float4; 8 per thread, all front-batched.
    float4 v[8];
    #pragma unroll
    for (int k = 0; k < 8; k++)
        v[k] = p[tid + k * THREADS];

    float s = 0.0f;
    #pragma unroll
    for (int k = 0; k < 8; k++)
        s += (v[k].x + v[k].y) + (v[k].z + v[k].w);

    #pragma unroll
    for (int off = 16; off > 0; off >>= 1)
        s += __shfl_xor_sync(0xFFFFFFFFu, s, off);

    __shared__ float warp_sums[THREADS / 32];
    const int lane = tid & 31, wid = tid >> 5;
    if (lane == 0) warp_sums[wid] = s;
    __syncthreads();

    if (wid == 0) {
        float t = (lane < THREADS / 32) ? warp_sums[lane] : 0.0f;
        #pragma unroll
        for (int off = 4; off > 0; off >>= 1)
            t += __shfl_xor_sync(0xFFFFFFFFu, t, off);
        if (lane == 0)
            out[0] = t * (1.0f / (float)B_DIM);
    }
}

extern "C" void kernel_launch(void* const* d_in, const int* in_sizes, int n_in,
                              void* d_out, int out_size)
{
    const float* inputs = (const float*)d_in[0];
    const int* targets = (const int*)d_in[1];
    float* out = (float*)d_out;

    ems_row_kernel<<<B_DIM, THREADS>>>(inputs, targets);
    ems_reduce_kernel<<<1, THREADS>>>(out);
}